// round 7
// baseline (speedup 1.0000x reference)
#include <cuda_runtime.h>
#include <cuda_fp16.h>
#include <cuda_bf16.h>
#include <cstdint>

#define N_NODES_MAX 50000
#define D 64

// Per-node record, 256 B:
//   halves [0..63]   = G = feat@W1 (fp16), natural column order
//   halves [64..127] = feat (fp16), PERMUTED: pos 64+8q+j holds
//                      feat[4q+j] for j<4, feat[32+4q+(j-4)] for j>=4
// so edge-lane l reads G cols [8l..8l+8) and its 8 feat cols each as ONE uint4.
__device__ __half g_rec[N_NODES_MAX * 128];
__device__ int g_idx_is64;

// ---------------------------------------------------------------------------
// Node transform + record build. One warp does 4 rows; lane owns G columns
// (2*lane, 2*lane+1). Thread 0 detects index dtype.
// ---------------------------------------------------------------------------
__global__ void node_gemm_kernel(const float* __restrict__ feat,
                                 const float* __restrict__ W1,
                                 int n_nodes,
                                 const long long* __restrict__ src_probe,
                                 int n_edges) {
    __shared__ float Ws[D * D];
    int tid = threadIdx.x;
    int gtid = blockIdx.x * blockDim.x + tid;

    if (gtid == 0) {
        int is64 = 1;
        int m = n_edges < 16 ? n_edges : 16;
        for (int i = 0; i < m; i++) {
            long long v = src_probe[i];
            if (v < 0 || v >= (long long)n_nodes) { is64 = 0; break; }
        }
        g_idx_is64 = is64;
    }

    for (int i = tid; i < D * D; i += blockDim.x) Ws[i] = W1[i];
    __syncthreads();

    int lane = tid & 31;
    int warpGlobal = gtid >> 5;
    int totalWarps = (int)((gridDim.x * blockDim.x) >> 5);
    int c0 = 2 * lane;
    int posA = 64 + 8 * (lane >> 2) + (lane & 3);
    int posB = posA + 4;

    for (int base = warpGlobal * 4; base < n_nodes; base += totalWarps * 4) {
        float fa[4], fb[4];
#pragma unroll
        for (int r = 0; r < 4; r++) {
            int row = base + r;
            if (row < n_nodes) {
                fa[r] = feat[row * D + lane];
                fb[r] = feat[row * D + 32 + lane];
            } else {
                fa[r] = 0.f; fb[r] = 0.f;
            }
        }
        float a0[4] = {0.f, 0.f, 0.f, 0.f};
        float a1[4] = {0.f, 0.f, 0.f, 0.f};
#pragma unroll
        for (int k = 0; k < 32; k++) {
            float w0 = Ws[k * D + c0];
            float w1 = Ws[k * D + c0 + 1];
#pragma unroll
            for (int r = 0; r < 4; r++) {
                float v = __shfl_sync(0xffffffffu, fa[r], k);
                a0[r] = fmaf(v, w0, a0[r]);
                a1[r] = fmaf(v, w1, a1[r]);
            }
        }
#pragma unroll
        for (int k = 0; k < 32; k++) {
            float w0 = Ws[(k + 32) * D + c0];
            float w1 = Ws[(k + 32) * D + c0 + 1];
#pragma unroll
            for (int r = 0; r < 4; r++) {
                float v = __shfl_sync(0xffffffffu, fb[r], k);
                a0[r] = fmaf(v, w0, a0[r]);
                a1[r] = fmaf(v, w1, a1[r]);
            }
        }
#pragma unroll
        for (int r = 0; r < 4; r++) {
            int row = base + r;
            if (row < n_nodes) {
                ((__half2*)g_rec)[row * 64 + lane] = __floats2half2_rn(a0[r], a1[r]);
                g_rec[row * 128 + posA] = __float2half_rn(fa[r]);
                g_rec[row * 128 + posB] = __float2half_rn(fb[r]);
            }
        }
    }
}

// ---------------------------------------------------------------------------
// Edge kernel with TMA bulk stores.
// Block processes tiles of 64 contiguous edges (16 KB of output):
//   - 32 groups x 2 edges/group compute into an SMEM staging buffer
//   - one thread flushes the tile with cp.async.bulk (SMEM -> GMEM),
//     double-buffered, so output stores never touch the L1tex path.
// Gathers: gs, gd, fd = one uint4 (16 B) per lane each.
// Partial tail tiles fall back to direct STG.
// ---------------------------------------------------------------------------
#define EDGES_PER_TILE 64
#define TILE_BYTES (EDGES_PER_TILE * D * 4)   // 16384

__global__ void __launch_bounds__(256, 4)
edge_kernel(const void* __restrict__ src_idx,
            const void* __restrict__ dst_idx,
            const float* __restrict__ b1,
            const float* __restrict__ W2,
            const float* __restrict__ b2,
            float* __restrict__ out,
            int n_edges) {
    __shared__ float4 obuf[2][EDGES_PER_TILE * 16];   // 2 x 16 KB

    const int tid = threadIdx.x;
    const int l = tid & 7;
    const int group = tid >> 3;                       // 0..31

    const float4* W24 = (const float4*)W2;
    float4 b1a = __ldg(&((const float4*)b1)[2 * l]);
    float4 b1b = __ldg(&((const float4*)b1)[2 * l + 1]);
    float4 w2a = __ldg(&W24[2 * l]);
    float4 w2b = __ldg(&W24[2 * l + 1]);
    float b2v = __ldg(&b2[0]);
    __half2 hb0 = __floats2half2_rn(b1a.x, b1a.y);
    __half2 hb1 = __floats2half2_rn(b1a.z, b1a.w);
    __half2 hb2 = __floats2half2_rn(b1b.x, b1b.y);
    __half2 hb3 = __floats2half2_rn(b1b.z, b1b.w);
    const __half2 hz = __float2half2_rn(0.f);
    const int is64 = g_idx_is64;

    const uint4* R16 = (const uint4*)g_rec;
    float4* O4 = (float4*)out;

    const int n_tiles = (n_edges + EDGES_PER_TILE - 1) / EDGES_PER_TILE;
    int buf = 0;

    for (int tile = blockIdx.x; tile < n_tiles; tile += gridDim.x) {
        int tileBase = tile * EDGES_PER_TILE;
        bool fullTile = (tileBase + EDGES_PER_TILE <= n_edges);

        if (fullTile) {
            // Ensure this buffer's previous bulk-store read has completed
            // (at most one other group outstanding = the other buffer).
            if (tid == 0)
                asm volatile("cp.async.bulk.wait_group.read 1;" ::: "memory");
            __syncthreads();
        }

        int e0 = tileBase + group * 2;
        int e1 = e0 + 1;
        bool hasA = (e0 < n_edges);
        bool hasB = (e1 < n_edges);

        long long sA = 0, dA = 0, sB = 0, dB = 0;
        if (hasA) {
            if (is64) {
                longlong2 sp = __ldg(&((const longlong2*)src_idx)[e0 >> 1]);
                longlong2 dp = __ldg(&((const longlong2*)dst_idx)[e0 >> 1]);
                sA = sp.x; dA = dp.x; sB = sp.y; dB = dp.y;
            } else {
                int2 sp = __ldg(&((const int2*)src_idx)[e0 >> 1]);
                int2 dp = __ldg(&((const int2*)dst_idx)[e0 >> 1]);
                sA = sp.x; dA = dp.x; sB = sp.y; dB = dp.y;
            }
        }

        uint4 gsA, gdA, fdA, gsB, gdB, fdB;
        if (hasA) {
            gsA = __ldg(&R16[sA * 16 + l]);
            gdA = __ldg(&R16[dA * 16 + l]);
            fdA = __ldg(&R16[dA * 16 + 8 + l]);
        }
        if (hasB) {
            gsB = __ldg(&R16[sB * 16 + l]);
            gdB = __ldg(&R16[dB * 16 + l]);
            fdB = __ldg(&R16[dB * 16 + 8 + l]);
        }

#define EDGE_COMPUTE(GS, GD, FD, OA, OB)                                       \
        {                                                                      \
            __half2 h0 = __hmax2(__hadd2(__hsub2(*(const __half2*)&GS.x,       \
                                                 *(const __half2*)&GD.x), hb0), hz); \
            __half2 h1 = __hmax2(__hadd2(__hsub2(*(const __half2*)&GS.y,       \
                                                 *(const __half2*)&GD.y), hb1), hz); \
            __half2 h2 = __hmax2(__hadd2(__hsub2(*(const __half2*)&GS.z,       \
                                                 *(const __half2*)&GD.z), hb2), hz); \
            __half2 h3 = __hmax2(__hadd2(__hsub2(*(const __half2*)&GS.w,       \
                                                 *(const __half2*)&GD.w), hb3), hz); \
            float2 p0 = __half22float2(h0);                                    \
            float2 p1 = __half22float2(h1);                                    \
            float2 p2 = __half22float2(h2);                                    \
            float2 p3 = __half22float2(h3);                                    \
            float p = p0.x * w2a.x;                                            \
            p = fmaf(p0.y, w2a.y, p); p = fmaf(p1.x, w2a.z, p);                \
            p = fmaf(p1.y, w2a.w, p); p = fmaf(p2.x, w2b.x, p);                \
            p = fmaf(p2.y, w2b.y, p); p = fmaf(p3.x, w2b.z, p);                \
            p = fmaf(p3.y, w2b.w, p);                                          \
            p += __shfl_xor_sync(0xffffffffu, p, 1, 8);                        \
            p += __shfl_xor_sync(0xffffffffu, p, 2, 8);                        \
            p += __shfl_xor_sync(0xffffffffu, p, 4, 8);                        \
            float a = __expf(-fmaxf(p + b2v, 0.f));                            \
            float2 f0 = __half22float2(*(const __half2*)&FD.x);                \
            float2 f1 = __half22float2(*(const __half2*)&FD.y);                \
            float2 f2 = __half22float2(*(const __half2*)&FD.z);                \
            float2 f3 = __half22float2(*(const __half2*)&FD.w);                \
            OA = make_float4(a * f0.x, a * f0.y, a * f1.x, a * f1.y);          \
            OB = make_float4(a * f2.x, a * f2.y, a * f3.x, a * f3.y);          \
        }

        if (fullTile) {
            int eLocalA = group * 2;
            float4* bufp = obuf[buf];
            {
                float4 oA, oB;
                EDGE_COMPUTE(gsA, gdA, fdA, oA, oB)
                bufp[eLocalA * 16 + l] = oA;
                bufp[eLocalA * 16 + l + 8] = oB;
            }
            {
                float4 oA, oB;
                EDGE_COMPUTE(gsB, gdB, fdB, oA, oB)
                bufp[(eLocalA + 1) * 16 + l] = oA;
                bufp[(eLocalA + 1) * 16 + l + 8] = oB;
            }
            __syncthreads();
            if (tid == 0) {
                uint32_t saddr;
                asm("{ .reg .u64 t; cvta.to.shared.u64 t, %1; cvt.u32.u64 %0, t; }"
                    : "=r"(saddr) : "l"((const void*)bufp));
                asm volatile("fence.proxy.async.shared::cta;" ::: "memory");
                asm volatile(
                    "cp.async.bulk.global.shared::cta.bulk_group [%0], [%1], %2;"
                    :: "l"(out + (long long)tileBase * D), "r"(saddr),
                       "r"((uint32_t)TILE_BYTES)
                    : "memory");
                asm volatile("cp.async.bulk.commit_group;" ::: "memory");
            }
            buf ^= 1;
        } else {
            // partial tail tile: direct stores
            if (hasA) {
                float4 oA, oB;
                EDGE_COMPUTE(gsA, gdA, fdA, oA, oB)
                long long ob = (long long)e0 * 16;
                O4[ob + l] = oA;
                O4[ob + l + 8] = oB;
            }
            if (hasB) {
                float4 oA, oB;
                EDGE_COMPUTE(gsB, gdB, fdB, oA, oB)
                long long ob = (long long)e1 * 16;
                O4[ob + l] = oA;
                O4[ob + l + 8] = oB;
            }
        }
#undef EDGE_COMPUTE
    }

    // drain all outstanding bulk stores before exit
    if (tid == 0)
        asm volatile("cp.async.bulk.wait_group.read 0;" ::: "memory");
}

// ---------------------------------------------------------------------------
// kernel_launch — inputs (metadata order):
//   0 features [50000,64] f32
//   1 src_idx  [800000]   int64 (or int32, detected)
//   2 dst_idx  [800000]   int64/int32
//   3 W1 [64,64] f32   4 b1 [64] f32   5 W2 [64,1] f32   6 b2 [1] f32
// output: [800000, 64] f32
// ---------------------------------------------------------------------------
extern "C" void kernel_launch(void* const* d_in, const int* in_sizes, int n_in,
                              void* d_out, int out_size) {
    const float* feat = (const float*)d_in[0];
    const void*  src  = d_in[1];
    const void*  dst  = d_in[2];
    const float* W1   = (const float*)d_in[3];
    const float* b1   = (const float*)d_in[4];
    const float* W2   = (const float*)d_in[5];
    const float* b2   = (const float*)d_in[6];
    float* out = (float*)d_out;

    int n_nodes = in_sizes[0] / D;
    int n_edges = in_sizes[1];

    int gemm_warptasks = (n_nodes + 3) / 4;
    int gemm_blocks = (gemm_warptasks + 7) / 8;   // 8 warps/block
    node_gemm_kernel<<<gemm_blocks, 256>>>(feat, W1, n_nodes,
                                           (const long long*)src, n_edges);

    edge_kernel<<<1184, 256>>>(src, dst, b1, W2, b2, out, n_edges);
}

// round 8
// speedup vs baseline: 1.2583x; 1.2583x over previous
#include <cuda_runtime.h>
#include <cuda_fp16.h>
#include <cuda_bf16.h>
#include <cstdint>

#define N_NODES_MAX 50000
#define D 64

// Per-node record, 256 B:
//   halves [0..63]   = G = feat@W1 (fp16), natural column order
//   halves [64..127] = feat (fp16), PERMUTED: pos 64+8q+j holds
//                      feat[4q+j] for j<4, feat[32+4q+(j-4)] for j>=4
// Edge-lane l reads G cols [8l..8l+8) and its 8 feat cols each as ONE uint4.
__device__ __half g_rec[N_NODES_MAX * 128];
__device__ int g_idx_is64;

// ---------------------------------------------------------------------------
// Node GEMM via tensor cores (mma.sync m16n8k16, fp16 inputs, fp32 accum).
// Block = 128 threads (4 warps). Warp processes one 16-row tile per iteration:
//   32 HMMA (8 n-tiles x 4 k-tiles) -> G fp16, plus feat->fp16 permuted copy.
// W1 is pre-packed into per-lane B fragments in smem (warp w builds k-tile w).
// Thread 0 of block 0 also detects index dtype.
// ---------------------------------------------------------------------------
__global__ void __launch_bounds__(128)
node_gemm_kernel(const float* __restrict__ feat,
                 const float* __restrict__ W1,
                 int n_nodes,
                 const long long* __restrict__ src_probe,
                 int n_edges) {
    // Bf[kt][nt][lane][0..1]: two b32 regs of the B fragment
    __shared__ uint32_t Bf[4][8][32][2];

    const int tid = threadIdx.x;
    const int w = tid >> 5;          // warp id 0..3
    const int lane = tid & 31;
    const int g = lane >> 2;         // groupID 0..7
    const int tig = lane & 3;        // thread in group 0..3

    if (blockIdx.x == 0 && tid == 0) {
        int is64 = 1;
        int m = n_edges < 16 ? n_edges : 16;
        for (int i = 0; i < m; i++) {
            long long v = src_probe[i];
            if (v < 0 || v >= (long long)n_nodes) { is64 = 0; break; }
        }
        g_idx_is64 = is64;
    }

    // Build B fragments for k-tile = w. B frag layout (m16n8k16):
    //   b0=(k=2tig, n=g) b1=(k=2tig+1) b2=(k=2tig+8) b3=(k=2tig+9), n = nt*8+g
    {
        int k0 = w * 16 + 2 * tig;
#pragma unroll
        for (int nt = 0; nt < 8; nt++) {
            int n = nt * 8 + g;
            __half2 b01 = __floats2half2_rn(W1[k0 * 64 + n], W1[(k0 + 1) * 64 + n]);
            __half2 b23 = __floats2half2_rn(W1[(k0 + 8) * 64 + n], W1[(k0 + 9) * 64 + n]);
            Bf[w][nt][lane][0] = *(uint32_t*)&b01;
            Bf[w][nt][lane][1] = *(uint32_t*)&b23;
        }
    }
    __syncthreads();

    const int n_tiles = n_nodes >> 4;            // 3125 (50000 % 16 == 0)
    const int warpsTotal = (int)gridDim.x * 4;

    for (int t = (int)blockIdx.x * 4 + w; t < n_tiles; t += warpsTotal) {
        int rowBase = t * 16;
        int r0 = rowBase + g;
        int r1 = r0 + 8;

        // A fragments: a[kt][0]={r0, col,col+1} a[1]={r1,col,col+1}
        //              a[2]={r0,col+8,+9}       a[3]={r1,col+8,+9}
        uint32_t a[4][4];
#pragma unroll
        for (int kt = 0; kt < 4; kt++) {
            int col = kt * 16 + 2 * tig;
            float2 f0 = *(const float2*)&feat[r0 * 64 + col];
            float2 f1 = *(const float2*)&feat[r1 * 64 + col];
            float2 f2 = *(const float2*)&feat[r0 * 64 + col + 8];
            float2 f3 = *(const float2*)&feat[r1 * 64 + col + 8];
            __half2 h0 = __floats2half2_rn(f0.x, f0.y);
            __half2 h1 = __floats2half2_rn(f1.x, f1.y);
            __half2 h2 = __floats2half2_rn(f2.x, f2.y);
            __half2 h3 = __floats2half2_rn(f3.x, f3.y);
            a[kt][0] = *(uint32_t*)&h0;
            a[kt][1] = *(uint32_t*)&h1;
            a[kt][2] = *(uint32_t*)&h2;
            a[kt][3] = *(uint32_t*)&h3;
        }

        __half2* GR = (__half2*)g_rec;
#pragma unroll
        for (int nt = 0; nt < 8; nt++) {
            float d0 = 0.f, d1 = 0.f, d2 = 0.f, d3 = 0.f;
#pragma unroll
            for (int kt = 0; kt < 4; kt++) {
                asm volatile(
                    "mma.sync.aligned.m16n8k16.row.col.f32.f16.f16.f32 "
                    "{%0,%1,%2,%3}, {%4,%5,%6,%7}, {%8,%9}, {%0,%1,%2,%3};"
                    : "+f"(d0), "+f"(d1), "+f"(d2), "+f"(d3)
                    : "r"(a[kt][0]), "r"(a[kt][1]), "r"(a[kt][2]), "r"(a[kt][3]),
                      "r"(Bf[kt][nt][lane][0]), "r"(Bf[kt][nt][lane][1]));
            }
            // D frag: c0=(g,2tig) c1=(g,2tig+1) c2=(g+8,2tig) c3=(g+8,2tig+1)
            GR[r0 * 64 + nt * 4 + tig] = __floats2half2_rn(d0, d1);
            GR[r1 * 64 + nt * 4 + tig] = __floats2half2_rn(d2, d3);
        }

        // feat -> fp16, permuted, into record halves [64..127].
        // lane: rowOff = lane>>1 (0..15), half = lane&1
        {
            int row = rowBase + (lane >> 1);
            int hf = lane & 1;
#pragma unroll
            for (int q = 0; q < 8; q++) {
                int colBase = hf ? (32 + 4 * q) : (4 * q);
                float4 f = *(const float4*)&feat[row * 64 + colBase];
                __half2 h01 = __floats2half2_rn(f.x, f.y);
                __half2 h23 = __floats2half2_rn(f.z, f.w);
                uint2 u;
                u.x = *(uint32_t*)&h01;
                u.y = *(uint32_t*)&h23;
                int pos = row * 128 + 64 + 8 * q + (hf ? 4 : 0);
                *(uint2*)&g_rec[pos] = u;
            }
        }
    }
}

// ---------------------------------------------------------------------------
// Edge kernel: 8 lanes per edge, 2 edges per iteration (ILP x2).  R5 structure:
// fp32 h math, direct coalesced STG. fd is ONE uint4 (permuted record).
//   out: lane l writes float4 slots l and l+8 -> one full 128B line per instr.
// ---------------------------------------------------------------------------
__global__ void __launch_bounds__(256, 4)
edge_kernel(const void* __restrict__ src_idx,
            const void* __restrict__ dst_idx,
            const float* __restrict__ b1,
            const float* __restrict__ W2,
            const float* __restrict__ b2,
            float* __restrict__ out,
            int n_edges) {
    const int l = threadIdx.x & 7;
    const int groupInBlock = threadIdx.x >> 3;
    const int gid = (int)blockIdx.x * 32 + groupInBlock;
    const int totalGroups = (int)gridDim.x * 32;

    const float4* B14 = (const float4*)b1;
    const float4* W24 = (const float4*)W2;
    float4 b1a = __ldg(&B14[2 * l]);
    float4 b1b = __ldg(&B14[2 * l + 1]);
    float4 w2a = __ldg(&W24[2 * l]);
    float4 w2b = __ldg(&W24[2 * l + 1]);
    float b2v = __ldg(&b2[0]);
    const int is64 = g_idx_is64;

    const uint4* R16 = (const uint4*)g_rec;   // 16 uint4/node: [0..7]=G, [8..15]=F(perm)
    float4* O4 = (float4*)out;

    for (int e0 = 2 * gid; e0 < n_edges; e0 += 2 * totalGroups) {
        int e1 = e0 + 1;
        bool hasB = (e1 < n_edges);

        long long sA, dA, sB = 0, dB = 0;
        if (is64) {
            longlong2 sp = __ldg(&((const longlong2*)src_idx)[e0 >> 1]);
            longlong2 dp = __ldg(&((const longlong2*)dst_idx)[e0 >> 1]);
            sA = sp.x; dA = dp.x; sB = sp.y; dB = dp.y;
        } else {
            int2 sp = __ldg(&((const int2*)src_idx)[e0 >> 1]);
            int2 dp = __ldg(&((const int2*)dst_idx)[e0 >> 1]);
            sA = sp.x; dA = dp.x; sB = sp.y; dB = dp.y;
        }

        // Issue all gathers for both edges before any compute.
        uint4 gsA = __ldg(&R16[sA * 16 + l]);
        uint4 gdA = __ldg(&R16[dA * 16 + l]);
        uint4 fdA = __ldg(&R16[dA * 16 + 8 + l]);
        uint4 gsB, gdB, fdB;
        if (hasB) {
            gsB = __ldg(&R16[sB * 16 + l]);
            gdB = __ldg(&R16[dB * 16 + l]);
            fdB = __ldg(&R16[dB * 16 + 8 + l]);
        }

#define EDGE_BODY(GS, GD, FD, EIDX)                                            \
        {                                                                      \
            float2 s0 = __half22float2(*(const __half2*)&GS.x);                \
            float2 s1 = __half22float2(*(const __half2*)&GS.y);                \
            float2 s2 = __half22float2(*(const __half2*)&GS.z);                \
            float2 s3 = __half22float2(*(const __half2*)&GS.w);                \
            float2 dd0 = __half22float2(*(const __half2*)&GD.x);               \
            float2 dd1 = __half22float2(*(const __half2*)&GD.y);               \
            float2 dd2 = __half22float2(*(const __half2*)&GD.z);               \
            float2 dd3 = __half22float2(*(const __half2*)&GD.w);               \
            float h0 = fmaxf(s0.x - dd0.x + b1a.x, 0.f);                       \
            float h1 = fmaxf(s0.y - dd0.y + b1a.y, 0.f);                       \
            float h2 = fmaxf(s1.x - dd1.x + b1a.z, 0.f);                       \
            float h3 = fmaxf(s1.y - dd1.y + b1a.w, 0.f);                       \
            float h4 = fmaxf(s2.x - dd2.x + b1b.x, 0.f);                       \
            float h5 = fmaxf(s2.y - dd2.y + b1b.y, 0.f);                       \
            float h6 = fmaxf(s3.x - dd3.x + b1b.z, 0.f);                       \
            float h7 = fmaxf(s3.y - dd3.y + b1b.w, 0.f);                       \
            float p = h0 * w2a.x;                                              \
            p = fmaf(h1, w2a.y, p); p = fmaf(h2, w2a.z, p);                    \
            p = fmaf(h3, w2a.w, p); p = fmaf(h4, w2b.x, p);                    \
            p = fmaf(h5, w2b.y, p); p = fmaf(h6, w2b.z, p);                    \
            p = fmaf(h7, w2b.w, p);                                            \
            p += __shfl_xor_sync(0xffffffffu, p, 1, 8);                        \
            p += __shfl_xor_sync(0xffffffffu, p, 2, 8);                        \
            p += __shfl_xor_sync(0xffffffffu, p, 4, 8);                        \
            float aa = __expf(-fmaxf(p + b2v, 0.f));                           \
            float2 f0 = __half22float2(*(const __half2*)&FD.x);                \
            float2 f1 = __half22float2(*(const __half2*)&FD.y);                \
            float2 f2 = __half22float2(*(const __half2*)&FD.z);                \
            float2 f3 = __half22float2(*(const __half2*)&FD.w);                \
            float4 oA = make_float4(aa * f0.x, aa * f0.y, aa * f1.x, aa * f1.y); \
            float4 oB = make_float4(aa * f2.x, aa * f2.y, aa * f3.x, aa * f3.y); \
            long long ob = (long long)(EIDX) * 16;                             \
            O4[ob + l] = oA;                                                   \
            O4[ob + l + 8] = oB;                                               \
        }

        EDGE_BODY(gsA, gdA, fdA, e0)
        if (hasB) EDGE_BODY(gsB, gdB, fdB, e1)
#undef EDGE_BODY
    }
}

// ---------------------------------------------------------------------------
// kernel_launch — inputs (metadata order):
//   0 features [50000,64] f32
//   1 src_idx  [800000]   int64 (or int32, detected)
//   2 dst_idx  [800000]   int64/int32
//   3 W1 [64,64] f32   4 b1 [64] f32   5 W2 [64,1] f32   6 b2 [1] f32
// output: [800000, 64] f32
// ---------------------------------------------------------------------------
extern "C" void kernel_launch(void* const* d_in, const int* in_sizes, int n_in,
                              void* d_out, int out_size) {
    const float* feat = (const float*)d_in[0];
    const void*  src  = d_in[1];
    const void*  dst  = d_in[2];
    const float* W1   = (const float*)d_in[3];
    const float* b1   = (const float*)d_in[4];
    const float* W2   = (const float*)d_in[5];
    const float* b2   = (const float*)d_in[6];
    float* out = (float*)d_out;

    int n_nodes = in_sizes[0] / D;
    int n_edges = in_sizes[1];

    int n_tiles = n_nodes >> 4;                  // 3125
    int gemm_blocks = (n_tiles + 3) / 4;         // 1 warp per tile
    node_gemm_kernel<<<gemm_blocks, 128>>>(feat, W1, n_nodes,
                                           (const long long*)src, n_edges);

    edge_kernel<<<1184, 256>>>(src, dst, b1, W2, b2, out, n_edges);
}

// round 9
// speedup vs baseline: 1.3466x; 1.0702x over previous
#include <cuda_runtime.h>
#include <cuda_fp16.h>
#include <cuda_bf16.h>
#include <cstdint>

#define N_NODES_MAX 50000
#define D 64

// Per-node record, 256 B:
//   halves [0..63]   = G = feat@W1 (fp16), natural column order
//   halves [64..127] = feat (fp16), PERMUTED: pos 64+8q+j holds
//                      feat[4q+j] for j<4, feat[32+4q+(j-4)] for j>=4
// Edge-lane l reads G cols [8l..8l+8) and its 8 feat cols each as ONE uint4.
__device__ __half g_rec[N_NODES_MAX * 128];
__device__ int g_idx_is64;

// ---------------------------------------------------------------------------
// Node GEMM via tensor cores, fully smem-staged:
//   - 64-node tile of feat loaded ONCE, coalesced, converted to fp16 in sA
//   - m16n8k16 HMMA per warp (A from sA), D frags into padded sRec
//   - permuted F half built smem->smem from sA
//   - sRec flushed to g_rec with coalesced uint4 stores (full 128B lines)
// ---------------------------------------------------------------------------
#define SA_STRIDE 66    // halves; 132 B row -> 1-bank shift, conflict-free frags
#define SR_STRIDE 136   // halves; 272 B row -> 4-bank shift, 16B-aligned flush

__global__ void __launch_bounds__(128)
node_gemm_kernel(const float* __restrict__ feat,
                 const float* __restrict__ W1,
                 int n_nodes,
                 const long long* __restrict__ src_probe,
                 int n_edges) {
    __shared__ uint32_t Bf[4][8][32][2];           // 8 KB B fragments
    __shared__ __half sA[64 * SA_STRIDE];          // 8.25 KB fp16 feat tile
    __shared__ __half sRec[64 * SR_STRIDE];        // 17 KB record staging

    const int tid = threadIdx.x;
    const int w = tid >> 5;          // warp 0..3
    const int lane = tid & 31;
    const int g = lane >> 2;         // 0..7
    const int tig = lane & 3;        // 0..3

    if (blockIdx.x == 0 && tid == 0) {
        int is64 = 1;
        int m = n_edges < 16 ? n_edges : 16;
        for (int i = 0; i < m; i++) {
            long long v = src_probe[i];
            if (v < 0 || v >= (long long)n_nodes) { is64 = 0; break; }
        }
        g_idx_is64 = is64;
    }

    // Build B fragments for k-tile = w (validated mapping from R8):
    //   b0=(k=2tig, n) b1=(k+1) b2=(k+8) b3=(k+9), n = nt*8+g
    {
        int k0 = w * 16 + 2 * tig;
#pragma unroll
        for (int nt = 0; nt < 8; nt++) {
            int n = nt * 8 + g;
            __half2 b01 = __floats2half2_rn(W1[k0 * 64 + n], W1[(k0 + 1) * 64 + n]);
            __half2 b23 = __floats2half2_rn(W1[(k0 + 8) * 64 + n], W1[(k0 + 9) * 64 + n]);
            Bf[w][nt][lane][0] = *(uint32_t*)&b01;
            Bf[w][nt][lane][1] = *(uint32_t*)&b23;
        }
    }

    const int n_tiles = (n_nodes + 63) >> 6;       // 782
    for (int t = blockIdx.x; t < n_tiles; t += gridDim.x) {
        const int base = t * 64;
        const int rows = min(64, n_nodes - base);

        __syncthreads();   // protect sA/sRec reuse across iterations + Bf ready

        // ---- load feat tile, coalesced float4, convert to fp16 in sA ----
#pragma unroll
        for (int p = 0; p < 8; p++) {
            int flat = p * 128 + tid;              // 0..1023 over 64 rows x 16 u4
            int node = flat >> 4;
            int c = flat & 15;                     // float4 index within row
            float4 f;
            if (node < rows) f = __ldg(&((const float4*)feat)[(long long)(base + node) * 16 + c]);
            else             f = make_float4(0.f, 0.f, 0.f, 0.f);
            __half2 h01 = __floats2half2_rn(f.x, f.y);
            __half2 h23 = __floats2half2_rn(f.z, f.w);
            __half* dstp = &sA[node * SA_STRIDE + c * 4];
            *(__half2*)(dstp)     = h01;           // 4B stores (row stride not 8B-aligned)
            *(__half2*)(dstp + 2) = h23;
        }
        __syncthreads();

        // ---- MMA: warp w computes rows w*16 .. w*16+15 ----
        {
            int r0 = w * 16 + g;
            int r1 = r0 + 8;
            uint32_t a[4][4];
#pragma unroll
            for (int kt = 0; kt < 4; kt++) {
                int col = kt * 16 + 2 * tig;
                a[kt][0] = *(uint32_t*)&sA[r0 * SA_STRIDE + col];
                a[kt][1] = *(uint32_t*)&sA[r1 * SA_STRIDE + col];
                a[kt][2] = *(uint32_t*)&sA[r0 * SA_STRIDE + col + 8];
                a[kt][3] = *(uint32_t*)&sA[r1 * SA_STRIDE + col + 8];
            }
#pragma unroll
            for (int nt = 0; nt < 8; nt++) {
                float d0 = 0.f, d1 = 0.f, d2 = 0.f, d3 = 0.f;
#pragma unroll
                for (int kt = 0; kt < 4; kt++) {
                    asm volatile(
                        "mma.sync.aligned.m16n8k16.row.col.f32.f16.f16.f32 "
                        "{%0,%1,%2,%3}, {%4,%5,%6,%7}, {%8,%9}, {%0,%1,%2,%3};"
                        : "+f"(d0), "+f"(d1), "+f"(d2), "+f"(d3)
                        : "r"(a[kt][0]), "r"(a[kt][1]), "r"(a[kt][2]), "r"(a[kt][3]),
                          "r"(Bf[kt][nt][lane][0]), "r"(Bf[kt][nt][lane][1]));
                }
                // D frag: (g, 2tig),(g,2tig+1) and (g+8, ...)
                int cc = nt * 8 + 2 * tig;
                *(__half2*)&sRec[r0 * SR_STRIDE + cc] = __floats2half2_rn(d0, d1);
                *(__half2*)&sRec[r1 * SR_STRIDE + cc] = __floats2half2_rn(d2, d3);
            }
        }

        // ---- permuted F half: smem -> smem (thread: node=tid/2, hf=tid&1) ----
        {
            int node = tid >> 1;
            int hf = tid & 1;
            const __half* srow = &sA[node * SA_STRIDE + (hf ? 32 : 0)];
            __half* drow = &sRec[node * SR_STRIDE + 64 + (hf ? 4 : 0)];
#pragma unroll
            for (int q = 0; q < 8; q++) {
                __half2 v0 = *(const __half2*)&srow[4 * q];
                __half2 v1 = *(const __half2*)&srow[4 * q + 2];
                *(__half2*)&drow[8 * q]     = v0;
                *(__half2*)&drow[8 * q + 2] = v1;
            }
        }
        __syncthreads();

        // ---- flush sRec -> g_rec, coalesced uint4 (full 128B lines) ----
#pragma unroll
        for (int p = 0; p < 8; p++) {
            int flat = p * 128 + tid;              // 64 rows x 16 uint4
            int node = flat >> 4;
            int c = flat & 15;
            if (node < rows) {
                uint4 v = *(const uint4*)&sRec[node * SR_STRIDE + c * 8];
                ((uint4*)g_rec)[(long long)(base + node) * 16 + c] = v;
            }
        }
    }
}

// ---------------------------------------------------------------------------
// Edge kernel (unchanged from R8 — at the LTS roofline):
// 8 lanes/edge, 2 edges/iteration, fp32 h math, direct coalesced STG.
// ---------------------------------------------------------------------------
__global__ void __launch_bounds__(256, 4)
edge_kernel(const void* __restrict__ src_idx,
            const void* __restrict__ dst_idx,
            const float* __restrict__ b1,
            const float* __restrict__ W2,
            const float* __restrict__ b2,
            float* __restrict__ out,
            int n_edges) {
    const int l = threadIdx.x & 7;
    const int groupInBlock = threadIdx.x >> 3;
    const int gid = (int)blockIdx.x * 32 + groupInBlock;
    const int totalGroups = (int)gridDim.x * 32;

    const float4* B14 = (const float4*)b1;
    const float4* W24 = (const float4*)W2;
    float4 b1a = __ldg(&B14[2 * l]);
    float4 b1b = __ldg(&B14[2 * l + 1]);
    float4 w2a = __ldg(&W24[2 * l]);
    float4 w2b = __ldg(&W24[2 * l + 1]);
    float b2v = __ldg(&b2[0]);
    const int is64 = g_idx_is64;

    const uint4* R16 = (const uint4*)g_rec;
    float4* O4 = (float4*)out;

    for (int e0 = 2 * gid; e0 < n_edges; e0 += 2 * totalGroups) {
        int e1 = e0 + 1;
        bool hasB = (e1 < n_edges);

        long long sA, dA, sB = 0, dB = 0;
        if (is64) {
            longlong2 sp = __ldg(&((const longlong2*)src_idx)[e0 >> 1]);
            longlong2 dp = __ldg(&((const longlong2*)dst_idx)[e0 >> 1]);
            sA = sp.x; dA = dp.x; sB = sp.y; dB = dp.y;
        } else {
            int2 sp = __ldg(&((const int2*)src_idx)[e0 >> 1]);
            int2 dp = __ldg(&((const int2*)dst_idx)[e0 >> 1]);
            sA = sp.x; dA = dp.x; sB = sp.y; dB = dp.y;
        }

        uint4 gsA = __ldg(&R16[sA * 16 + l]);
        uint4 gdA = __ldg(&R16[dA * 16 + l]);
        uint4 fdA = __ldg(&R16[dA * 16 + 8 + l]);
        uint4 gsB, gdB, fdB;
        if (hasB) {
            gsB = __ldg(&R16[sB * 16 + l]);
            gdB = __ldg(&R16[dB * 16 + l]);
            fdB = __ldg(&R16[dB * 16 + 8 + l]);
        }

#define EDGE_BODY(GS, GD, FD, EIDX)                                            \
        {                                                                      \
            float2 s0 = __half22float2(*(const __half2*)&GS.x);                \
            float2 s1 = __half22float2(*(const __half2*)&GS.y);                \
            float2 s2 = __half22float2(*(const __half2*)&GS.z);                \
            float2 s3 = __half22float2(*(const __half2*)&GS.w);                \
            float2 dd0 = __half22float2(*(const __half2*)&GD.x);               \
            float2 dd1 = __half22float2(*(const __half2*)&GD.y);               \
            float2 dd2 = __half22float2(*(const __half2*)&GD.z);               \
            float2 dd3 = __half22float2(*(const __half2*)&GD.w);               \
            float h0 = fmaxf(s0.x - dd0.x + b1a.x, 0.f);                       \
            float h1 = fmaxf(s0.y - dd0.y + b1a.y, 0.f);                       \
            float h2 = fmaxf(s1.x - dd1.x + b1a.z, 0.f);                       \
            float h3 = fmaxf(s1.y - dd1.y + b1a.w, 0.f);                       \
            float h4 = fmaxf(s2.x - dd2.x + b1b.x, 0.f);                       \
            float h5 = fmaxf(s2.y - dd2.y + b1b.y, 0.f);                       \
            float h6 = fmaxf(s3.x - dd3.x + b1b.z, 0.f);                       \
            float h7 = fmaxf(s3.y - dd3.y + b1b.w, 0.f);                       \
            float p = h0 * w2a.x;                                              \
            p = fmaf(h1, w2a.y, p); p = fmaf(h2, w2a.z, p);                    \
            p = fmaf(h3, w2a.w, p); p = fmaf(h4, w2b.x, p);                    \
            p = fmaf(h5, w2b.y, p); p = fmaf(h6, w2b.z, p);                    \
            p = fmaf(h7, w2b.w, p);                                            \
            p += __shfl_xor_sync(0xffffffffu, p, 1, 8);                        \
            p += __shfl_xor_sync(0xffffffffu, p, 2, 8);                        \
            p += __shfl_xor_sync(0xffffffffu, p, 4, 8);                        \
            float aa = __expf(-fmaxf(p + b2v, 0.f));                           \
            float2 f0 = __half22float2(*(const __half2*)&FD.x);                \
            float2 f1 = __half22float2(*(const __half2*)&FD.y);                \
            float2 f2 = __half22float2(*(const __half2*)&FD.z);                \
            float2 f3 = __half22float2(*(const __half2*)&FD.w);                \
            float4 oA = make_float4(aa * f0.x, aa * f0.y, aa * f1.x, aa * f1.y); \
            float4 oB = make_float4(aa * f2.x, aa * f2.y, aa * f3.x, aa * f3.y); \
            long long ob = (long long)(EIDX) * 16;                             \
            O4[ob + l] = oA;                                                   \
            O4[ob + l + 8] = oB;                                               \
        }

        EDGE_BODY(gsA, gdA, fdA, e0)
        if (hasB) EDGE_BODY(gsB, gdB, fdB, e1)
#undef EDGE_BODY
    }
}

// ---------------------------------------------------------------------------
// kernel_launch — inputs (metadata order):
//   0 features [50000,64] f32
//   1 src_idx  [800000]   int64 (or int32, detected)
//   2 dst_idx  [800000]   int64/int32
//   3 W1 [64,64] f32   4 b1 [64] f32   5 W2 [64,1] f32   6 b2 [1] f32
// output: [800000, 64] f32
// ---------------------------------------------------------------------------
extern "C" void kernel_launch(void* const* d_in, const int* in_sizes, int n_in,
                              void* d_out, int out_size) {
    const float* feat = (const float*)d_in[0];
    const void*  src  = d_in[1];
    const void*  dst  = d_in[2];
    const float* W1   = (const float*)d_in[3];
    const float* b1   = (const float*)d_in[4];
    const float* W2   = (const float*)d_in[5];
    const float* b2   = (const float*)d_in[6];
    float* out = (float*)d_out;

    int n_nodes = in_sizes[0] / D;
    int n_edges = in_sizes[1];

    int n_tiles = (n_nodes + 63) / 64;           // 782
    node_gemm_kernel<<<n_tiles, 128>>>(feat, W1, n_nodes,
                                       (const long long*)src, n_edges);

    edge_kernel<<<1184, 256>>>(src, dst, b1, W2, b2, out, n_edges);
}